// round 17
// baseline (speedup 1.0000x reference)
#include <cuda_runtime.h>
#include <cuda_fp16.h>
#include <math.h>

#define K 128
#define E 4096
#define M 512
#define NUM_UPDATE 3
#define THRESHOLD 0.05f
#define HOT 8
#define MAXNZ 32
#define CAP 1536                      // max active e per k (E*0.3 ~ 1229)
#define NBLKA (CAP / 256)             // 6 blocks per k (streaming steps)
#define NBLK0 (E / 256)               // 16 blocks per k (gather step)

// ---------------- device scratch ----------------
__device__ __align__(16) unsigned char g_nzpk[E * MAXNZ];
__device__ unsigned char g_cnt[E];
__device__ float4 g_cc[E];                    // (c0, c1, score, 1/d) per e
__device__ float  g_bz[E];                    // beta2 * Zc
__device__ unsigned short g_elist[K * CAP];   // compacted active e per k
__device__ unsigned short g_slot[(size_t)K * E]; // inverse map: slot or 0xFFFF
__device__ int    g_ecnt[K];                  // active count per k
__device__ float2 g_a12[K * CAP];             // (W*beta1, W*bz) at compact slots
__device__ uint4  g_bch[K * CAP];             // gathered B half8 at compact slots
__device__ uint4  g_dvh[E];                   // dval as half8 per e, per step
__device__ float2 g_icf[E];                   // (Ic, tailflag) per e, per step
__device__ float  g_u[K];
__device__ float  g_dv[K];
__device__ int    g_upd[K];
__device__ float  g_partial[K * NBLK0];
__device__ unsigned g_donek[NUM_UPDATE][K];   // per-k arrivals
__device__ unsigned g_done[NUM_UPDATE];       // per-step k-completions (K)

__device__ __forceinline__ float sigm_neg(float x) {
    return __fdividef(1.0f, 1.0f + __expf(x));  // sigmoid(-x)
}

__device__ __forceinline__ uint4 pack_half8(const float* v) {
    uint4 r;
    __half2 h;
    h = __floats2half2_rn(v[0], v[1]); r.x = *reinterpret_cast<unsigned*>(&h);
    h = __floats2half2_rn(v[2], v[3]); r.y = *reinterpret_cast<unsigned*>(&h);
    h = __floats2half2_rn(v[4], v[5]); r.z = *reinterpret_cast<unsigned*>(&h);
    h = __floats2half2_rn(v[6], v[7]); r.w = *reinterpret_cast<unsigned*>(&h);
    return r;
}

// ---------------- init0: nz lists, constants, dvh0, icf0, u0, counters,
//                  per-k compaction + inverse slot map (blocks 0..K-1) ----------------
// grid = E/8 = 512 blocks of 256 (warp per e)
__global__ void init0_kernel(const float* __restrict__ q_kn,
                             const float* __restrict__ U,
                             const int* __restrict__ stu_id,
                             const int* __restrict__ kn_id,
                             const float* __restrict__ gamma_c,
                             const float* __restrict__ dd,
                             const float* __restrict__ score,
                             const float* __restrict__ beta2,
                             const float* __restrict__ gs,
                             const float* __restrict__ A_emb,
                             const float* __restrict__ user) {
    int tid = threadIdx.x;
    int w = tid >> 5, l = tid & 31;
    int e = blockIdx.x * 8 + w;
    int stu = stu_id[0];

    __shared__ float sh_dv[8][HOT];
    if (l < HOT) sh_dv[w][l] = 0.0f;
    __syncwarp();

    int base = 0;
    float su = 0.0f;
#pragma unroll
    for (int r = 0; r < 4; r++) {
        int j = r * 32 + l;
        float q = q_kn[(size_t)e * K + j];
        unsigned m = __ballot_sync(0xFFFFFFFFu, q != 0.0f);
        if (q != 0.0f) {
            int pos = base + __popc(m & ((1u << l) - 1u));
            float u0j = U[(size_t)stu * K + j];
            if (pos < MAXNZ) g_nzpk[e * MAXNZ + pos] = (unsigned char)j;
            float dvj = u0j - 0.5f;
            dvj = (fabsf(dvj) > THRESHOLD) ? dvj : 0.0f;
            if (pos < HOT) sh_dv[w][pos] = dvj;
            su += u0j;
        }
        base += __popc(m);
    }
    su += __shfl_xor_sync(0xFFFFFFFFu, su, 16);
    su += __shfl_xor_sync(0xFFFFFFFFu, su, 8);
    su += __shfl_xor_sync(0xFFFFFFFFu, su, 4);
    su += __shfl_xor_sync(0xFFFFFFFFu, su, 2);
    su += __shfl_xor_sync(0xFFFFFFFFu, su, 1);
    __syncwarp();
    if (l == 0) {
        int cnt = base < MAXNZ ? base : MAXNZ;
        g_cnt[e] = (unsigned char)cnt;
        float invd = 1.0f / dd[e];
        float sc   = score[e];
        float x  = (gamma_c[e] * invd) * (sc - 0.5f);
        g_bz[e]  = beta2[e] * (sigm_neg(x) - 0.5f);
        float c0 = A_emb[3 * e + 0] * (1.0f - gs[2 * e + 0])
                 + A_emb[3 * e + 1] * (1.0f - gs[2 * e + 1]);
        float c1 = A_emb[3 * e + 2];
        g_cc[e] = make_float4(c0, c1, sc, invd);
        float t  = sc - su * invd;
        float Ic = sigm_neg(c0 + c1 * __expf(-t * t));
        g_icf[e] = make_float2(Ic, cnt > HOT ? 1.0f : 0.0f);
        g_dvh[e] = pack_half8(sh_dv[w]);
    }

    if (blockIdx.x == 0) {
        if (tid < NUM_UPDATE) g_done[tid] = 0u;
        for (int i = tid; i < NUM_UPDATE * K; i += 256)
            g_donek[i / K][i % K] = 0u;
        if (tid < K) {
            float u0 = U[(size_t)stu * K + tid];
            g_u[tid] = u0;
            float dv = u0 - 0.5f;
            g_dv[tid] = (fabsf(dv) > THRESHOLD) ? dv : 0.0f;
            g_upd[tid] = 0;
        }
        __syncthreads();
        if (tid < K) {
            int kn = kn_id[tid];
            if (kn >= 0 && kn < K) g_upd[kn] = 1;
        }
    }

    // ---- deterministic compaction + inverse slot map for k = blockIdx.x ----
    if (blockIdx.x < K) {
        int k = blockIdx.x;
        size_t kE = (size_t)k * E;
        __shared__ int warpcnt[8];
        // batch all 16 loads first: 1 exposed DRAM latency instead of 16
        float uv[E / 256];
#pragma unroll
        for (int r = 0; r < E / 256; r++) uv[r] = user[kE + r * 256 + tid];
        int total = 0;
        for (int r = 0; r < E / 256; r++) {
            int e2 = r * 256 + tid;
            bool p = uv[r] != 0.0f;
            unsigned m = __ballot_sync(0xFFFFFFFFu, p);
            if (l == 0) warpcnt[w] = __popc(m);
            __syncthreads();
            int off = total;
            for (int i = 0; i < w; i++) off += warpcnt[i];
            unsigned short sl = 0xFFFFu;
            if (p) {
                int pos = off + __popc(m & ((1u << l) - 1u));
                if (pos < CAP) {
                    g_elist[k * CAP + pos] = (unsigned short)e2;
                    sl = (unsigned short)pos;
                }
            }
            g_slot[kE + e2] = sl;
            int t2 = 0;
#pragma unroll
            for (int i = 0; i < 8; i++) t2 += warpcnt[i];
            total += t2;
            __syncthreads();
        }
        if (tid == 0) g_ecnt[k] = total < CAP ? total : CAP;
    }
}

// ---------------- pre: per-step dvh + icf from current g_u ----------------
// grid = 16 blocks of 256; 1 e per thread
__global__ void pre_kernel() {
    __shared__ float s_u[K];
    __shared__ float s_dv[K];
    int tid = threadIdx.x;
    if (tid < K) {
        float u = g_u[tid];
        s_u[tid] = u;
        s_dv[tid] = g_dv[tid];
    }
    __syncthreads();

    int e = blockIdx.x * 256 + tid;
    const uint4* pkp = (const uint4*)(g_nzpk + e * MAXNZ);
    uint4 p0 = pkp[0], p1 = pkp[1];
    unsigned pw[8] = {p0.x, p0.y, p0.z, p0.w, p1.x, p1.y, p1.z, p1.w};
    int cnt = g_cnt[e];
    float4 cc = g_cc[e];

    float su = 0.0f;
    float v[HOT];
#pragma unroll
    for (int i = 0; i < HOT; i++) {
        int j = (pw[i >> 2] >> ((i & 3) * 8)) & 0xFF;
        bool valid = i < cnt;
        v[i] = valid ? s_dv[j] : 0.0f;
        su += valid ? s_u[j] : 0.0f;
    }
    for (int i = HOT; i < cnt; i++) {
        int j = (pw[i >> 2] >> ((i & 3) * 8)) & 0xFF;
        su += s_u[j];
    }
    g_dvh[e] = pack_half8(v);
    float t  = cc.z - su * cc.w;
    float Ic = sigm_neg(cc.x + cc.y * __expf(-t * t));
    g_icf[e] = make_float2(Ic, cnt > HOT ? 1.0f : 0.0f);
}

// ---------------- big step kernel ----------------
// GATHER (step 0): ALL-PAIRS grid (NBLK0, K); flat 2-level load chain:
//   level 1: slot/nzpk/cnt/dvh/icf/W/beta1/bz (all direct-indexed, independent)
//   level 2: B gathers (active pairs only); writes compact bch/a12 at slot.
// !GATHER (steps 1,2): compact grid (NBLKA, K); streams bch/a12 + dvh/icf.
// Final step's epilogue block also runs predict.
template <int NB, bool GATHER>
__global__ __launch_bounds__(256) void big_kernel(const float* __restrict__ Bm,
                                                  const float* __restrict__ beta1,
                                                  const float* __restrict__ W,
                                                  const float* __restrict__ alpha,
                                                  const float* __restrict__ gamma_e,
                                                  const int* __restrict__ ex_id,
                                                  float* __restrict__ out,
                                                  int step) {
    int k = blockIdx.y;
    size_t kE = (size_t)k * E;
    int tid = threadIdx.x;

    float acc = 0.0f;

    if (GATHER) {
        int e = blockIdx.x * 256 + tid;
        // level-1 independent loads
        unsigned short slot = g_slot[kE + e];
        uint2 pk   = *(const uint2*)(g_nzpk + e * MAXNZ);
        int cnt    = g_cnt[e];
        uint4 dvr  = g_dvh[e];
        float2 icf = g_icf[e];
        float wv   = W[kE + e];
        float b1   = beta1[kE + e];
        float bz   = g_bz[e];

        if (slot != 0xFFFFu) {
            __half2* dh = reinterpret_cast<__half2*>(&dvr);
            float2 q0 = __half22float2(dh[0]);
            float2 q1 = __half22float2(dh[1]);
            float2 q2 = __half22float2(dh[2]);
            float2 q3 = __half22float2(dh[3]);
            float dv[HOT] = {q0.x, q0.y, q1.x, q1.y, q2.x, q2.y, q3.x, q3.y};
            const float* __restrict__ Brow = Bm + (kE + e) * K;
            unsigned pw0 = pk.x, pw1 = pk.y;
            float dot = 0.0f;
            float bc[HOT];
#pragma unroll
            for (int i = 0; i < HOT; i++) {
                int j = ((i < 4 ? pw0 : pw1) >> ((i & 3) * 8)) & 0xFF;
                bool g = (i < cnt) && (j != k);
                bc[i] = g ? __ldg(Brow + j) : 0.0f;
                dot += bc[i] * dv[i];
            }
            g_bch[k * CAP + slot] = pack_half8(bc);
            float2 a = make_float2(wv * b1, wv * bz);
            g_a12[k * CAP + slot] = a;

            if (icf.y != 0.0f) {   // rare tail
                const uint4* pkp = (const uint4*)(g_nzpk + e * MAXNZ);
                uint4 t0 = pkp[0], t1 = pkp[1];
                unsigned pw[8] = {t0.x, t0.y, t0.z, t0.w, t1.x, t1.y, t1.z, t1.w};
                for (int i = HOT; i < cnt; i++) {
                    int j = (pw[i >> 2] >> ((i & 3) * 8)) & 0xFF;
                    if (j != k) dot += __ldg(Brow + j) * g_dv[j];
                }
            }
            float gkc = sigm_neg(dot) - 1.0f;
            acc = icf.x * (a.x * gkc + a.y);
        }
    } else {
        int slot = blockIdx.x * 256 + tid;
        if (slot < g_ecnt[k]) {
            int e = g_elist[k * CAP + slot];
            uint4 dvr  = g_dvh[e];
            float2 icf = g_icf[e];
            uint4 rec  = g_bch[k * CAP + slot];
            float2 a   = g_a12[k * CAP + slot];
            __half2* dh = reinterpret_cast<__half2*>(&dvr);
            float2 q0 = __half22float2(dh[0]);
            float2 q1 = __half22float2(dh[1]);
            float2 q2 = __half22float2(dh[2]);
            float2 q3 = __half22float2(dh[3]);
            float dv[HOT] = {q0.x, q0.y, q1.x, q1.y, q2.x, q2.y, q3.x, q3.y};
            __half2* hp = reinterpret_cast<__half2*>(&rec);
            float2 p0 = __half22float2(hp[0]);
            float2 p1 = __half22float2(hp[1]);
            float2 p2 = __half22float2(hp[2]);
            float2 p3 = __half22float2(hp[3]);
            float dot = p0.x * dv[0] + p0.y * dv[1] + p1.x * dv[2] + p1.y * dv[3]
                      + p2.x * dv[4] + p2.y * dv[5] + p3.x * dv[6] + p3.y * dv[7];

            if (icf.y != 0.0f) {   // rare tail
                const uint4* pkp = (const uint4*)(g_nzpk + e * MAXNZ);
                uint4 t0 = pkp[0], t1 = pkp[1];
                unsigned pw[8] = {t0.x, t0.y, t0.z, t0.w, t1.x, t1.y, t1.z, t1.w};
                int cnt = g_cnt[e];
                const float* __restrict__ Brow = Bm + (kE + e) * K;
                for (int i = HOT; i < cnt; i++) {
                    int j = (pw[i >> 2] >> ((i & 3) * 8)) & 0xFF;
                    if (j != k) dot += __ldg(Brow + j) * g_dv[j];
                }
            }
            float gkc = sigm_neg(dot) - 1.0f;
            acc = icf.x * (a.x * gkc + a.y);
        }
    }

    // deterministic block reduction
    __shared__ float warpacc[8];
    int w = tid >> 5, l = tid & 31;
    acc += __shfl_xor_sync(0xFFFFFFFFu, acc, 16);
    acc += __shfl_xor_sync(0xFFFFFFFFu, acc, 8);
    acc += __shfl_xor_sync(0xFFFFFFFFu, acc, 4);
    acc += __shfl_xor_sync(0xFFFFFFFFu, acc, 2);
    acc += __shfl_xor_sync(0xFFFFFFFFu, acc, 1);
    if (l == 0) warpacc[w] = acc;
    __syncthreads();

    // hierarchical completion: per-k counter (NB) -> global (K)
    __shared__ bool is_last;
    if (tid == 0) {
        float s = 0.0f;
#pragma unroll
        for (int i = 0; i < 8; i++) s += warpacc[i];
        g_partial[k * NB + blockIdx.x] = s;
        __threadfence();
        bool last = false;
        unsigned tk = atomicAdd(&g_donek[step][k], 1u);
        if (tk == (unsigned)(NB - 1)) {
            unsigned g = atomicAdd(&g_done[step], 1u);
            last = (g == (unsigned)(K - 1));
        }
        is_last = last;
    }
    __syncthreads();
    if (!is_last) return;
    __threadfence();

    // ---- fused epilogue (one block): u update + diff norm + state outputs ----
    __shared__ float red[K];
    __shared__ float s_u[K];
    if (tid < K) {
        float s = 0.0f;
#pragma unroll
        for (int c = 0; c < NB; c++) s += g_partial[tid * NB + c];
        float u_old = g_u[tid];
        float u_new = sigm_neg(s);
        float un = g_upd[tid] ? u_new : u_old;
        float ddf = un - u_old;
        red[tid] = ddf * ddf;
        s_u[tid] = un;
        g_u[tid] = un;
        float dvn = un - 0.5f;
        g_dv[tid] = (fabsf(dvn) > THRESHOLD) ? dvn : 0.0f;
        if (step == NUM_UPDATE - 2) out[K + tid] = un;  // state_2nd_last
        if (step == NUM_UPDATE - 1) out[tid]     = un;  // state_last
    }
    __syncthreads();
#pragma unroll
    for (int off = 64; off > 0; off >>= 1) {
        if (tid < off && tid + off < K) red[tid] += red[tid + off];
        __syncthreads();
    }
    if (tid == 0) out[2 * K + M + step] = sqrtf(red[0]);

    // ---- final step: predict fused into epilogue block ----
    if (step == NUM_UPDATE - 1) {
#pragma unroll
        for (int r = 0; r < M / 256; r++) {
            int m = r * 256 + tid;
            int e2 = ex_id[m];
            const uint4* pkp = (const uint4*)(g_nzpk + e2 * MAXNZ);
            uint4 p0 = pkp[0], p1 = pkp[1];
            unsigned pw[8] = {p0.x, p0.y, p0.z, p0.w, p1.x, p1.y, p1.z, p1.w};
            int cnt2 = g_cnt[e2];
            float accv = 0.0f;
            for (int i = 0; i < cnt2; i++) {
                int j = (pw[i >> 2] >> ((i & 3) * 8)) & 0xFF;
                accv += s_u[j];
            }
            float Ukse = accv * g_cc[e2].w - 0.5f;
            out[2 * K + m] = sigm_neg(alpha[e2] * Ukse + gamma_e[e2]);
        }
    }
}

// ---------------- launch ----------------
extern "C" void kernel_launch(void* const* d_in, const int* in_sizes, int n_in,
                              void* d_out, int out_size) {
    const float* U       = (const float*)d_in[0];
    const float* W       = (const float*)d_in[1];
    const float* beta1   = (const float*)d_in[2];
    const float* beta2   = (const float*)d_in[3];
    const float* Bm      = (const float*)d_in[4];
    const float* gs      = (const float*)d_in[5];
    const float* A_emb   = (const float*)d_in[6];
    const float* gamma_c = (const float*)d_in[7];
    const float* gamma_e = (const float*)d_in[8];
    const float* alpha   = (const float*)d_in[9];
    const float* score   = (const float*)d_in[10];
    const float* user    = (const float*)d_in[11];
    const float* q_kn    = (const float*)d_in[12];
    const float* d       = (const float*)d_in[13];
    const int*   stu_id  = (const int*)d_in[14];
    const int*   kn_id   = (const int*)d_in[15];
    const int*   ex_id   = (const int*)d_in[16];
    float* out = (float*)d_out;

    init0_kernel<<<E / 8, 256>>>(q_kn, U, stu_id, kn_id, gamma_c, d, score,
                                 beta2, gs, A_emb, user);
    big_kernel<NBLK0, true><<<dim3(NBLK0, K), 256>>>(Bm, beta1, W, alpha, gamma_e, ex_id, out, 0);
    pre_kernel<<<16, 256>>>();
    big_kernel<NBLKA, false><<<dim3(NBLKA, K), 256>>>(Bm, beta1, W, alpha, gamma_e, ex_id, out, 1);
    pre_kernel<<<16, 256>>>();
    big_kernel<NBLKA, false><<<dim3(NBLKA, K), 256>>>(Bm, beta1, W, alpha, gamma_e, ex_id, out, 2);
}